// round 13
// baseline (speedup 1.0000x reference)
#include <cuda_runtime.h>

#define NN 100000
#define EE 1600000
#define HH 64
#define THV 0.7f
#define ATTV 0.2f
#define EPSV 1e-5f
#define SBLK 98
#define EB 1184
#define AGB 592

__device__ float g_buf[6][NN*HH];
__device__ float g_V[NN*HH];
__device__ unsigned g_sp[NN*32];          // bf16x2 spikes: lane l -> cols (2l, 2l+1)
__device__ int g_cnt1[NN], g_cnt2[NN];
__device__ int g_rowptr1[NN+1], g_cursor1[NN];
__device__ int g_rowptr2[NN+1], g_cursor2[NN];
__device__ long long g_e1[EE];            // {coef_bits:hi, src:lo}
__device__ long long g_e2[EE];            // masked edges only
__device__ float g_dis1[NN], g_dis2[NN];
__device__ double g_stats[18][2][HH];
__device__ float g_wsum[HH];
__device__ int g_agg1[SBLK], g_agg2[SBLK], g_flag[SBLK];

// ---------------- f32x2 helpers ----------------
__device__ __forceinline__ unsigned long long pk2(float x, float y) {
    unsigned long long r; asm("mov.b64 %0,{%1,%2};" : "=l"(r) : "f"(x), "f"(y)); return r;
}
__device__ __forceinline__ float2 up2(unsigned long long v) {
    float2 r; asm("mov.b64 {%0,%1},%2;" : "=f"(r.x), "=f"(r.y) : "l"(v)); return r;
}
__device__ __forceinline__ void fma2(unsigned long long& d, unsigned long long a, unsigned long long b) {
    asm("fma.rn.f32x2 %0,%1,%2,%0;" : "+l"(d) : "l"(a), "l"(b));
}

// ---------------- setup ----------------
__global__ void k_count(const int* __restrict__ ei, const int* __restrict__ mk,
                        const float* __restrict__ Wl) {
    int stride = gridDim.x * blockDim.x;
    for (int e = blockIdx.x * blockDim.x + threadIdx.x; e < EE; e += stride) {
        int dst = ei[EE + e];
        atomicAdd(&g_cnt1[dst], 1);
        if (mk[e]) atomicAdd(&g_cnt2[dst], 1);
    }
    if (blockIdx.x == 0 && threadIdx.x < HH) {
        float s = 0.f;
        for (int j = 0; j < HH; j++) s += Wl[threadIdx.x*HH + j];
        g_wsum[threadIdx.x] = s;
    }
}

__device__ __forceinline__ int blk_scan(int v, int t, int* sw) {
    int x = v;
    #pragma unroll
    for (int o = 1; o < 32; o <<= 1) {
        int y = __shfl_up_sync(0xffffffffu, x, o);
        if ((t & 31) >= o) x += y;
    }
    if ((t & 31) == 31) sw[t >> 5] = x;
    __syncthreads();
    if (t < 32) {
        int y = sw[t], z = y;
        #pragma unroll
        for (int o = 1; o < 32; o <<= 1) {
            int w = __shfl_up_sync(0xffffffffu, z, o);
            if (t >= o) z += w;
        }
        sw[t] = z - y;
    }
    __syncthreads();
    return x + sw[t >> 5];
}

__global__ void k_scan() {
    __shared__ int sw1[32], sw2[32];
    __shared__ int soff1, soff2;
    int t = threadIdx.x, b = blockIdx.x;
    int i = b * 1024 + t;
    int c1 = (i < NN) ? g_cnt1[i] : 0;
    int c2 = (i < NN) ? g_cnt2[i] : 0;
    int incl1 = blk_scan(c1, t, sw1);
    __syncthreads();
    int incl2 = blk_scan(c2, t, sw2);
    if (t == 1023) {
        atomicExch(&g_agg1[b], incl1);
        atomicExch(&g_agg2[b], incl2);
        __threadfence();
        atomicExch(&g_flag[b], 1);
    }
    if (t < 32) {
        int o1 = 0, o2 = 0;
        for (int j = t; j < b; j += 32) {
            while (atomicAdd(&g_flag[j], 0) == 0) { }
            o1 += atomicAdd(&g_agg1[j], 0);
            o2 += atomicAdd(&g_agg2[j], 0);
        }
        #pragma unroll
        for (int o = 16; o > 0; o >>= 1) {
            o1 += __shfl_down_sync(0xffffffffu, o1, o);
            o2 += __shfl_down_sync(0xffffffffu, o2, o);
        }
        if (t == 0) { soff1 = o1; soff2 = o2; }
    }
    __syncthreads();
    if (i < NN) {
        int r1 = soff1 + incl1 - c1;
        int r2 = soff2 + incl2 - c2;
        g_rowptr1[i] = r1; g_cursor1[i] = r1;
        g_rowptr2[i] = r2; g_cursor2[i] = r2;
        g_dis1[i] = rsqrtf(1.0f + (float)c1);
        g_dis2[i] = rsqrtf(1.0f + (float)c2);
    }
    if (b == SBLK - 1 && t == 1023) {
        g_rowptr1[NN] = soff1 + incl1;
        g_rowptr2[NN] = soff2 + incl2;
    }
}

__global__ void k_scatter(const int* __restrict__ ei, const int* __restrict__ mk) {
    int stride = gridDim.x * blockDim.x;
    for (int e = blockIdx.x * blockDim.x + threadIdx.x; e < EE; e += stride) {
        int src = ei[e], dst = ei[EE + e];
        float c1 = g_dis1[src] * g_dis1[dst];
        int p1 = atomicAdd(&g_cursor1[dst], 1);
        g_e1[p1] = ((long long)__float_as_int(c1) << 32) | (unsigned)src;
        if (mk[e]) {
            float c2 = g_dis2[src] * g_dis2[dst];
            int p2 = atomicAdd(&g_cursor2[dst], 1);
            g_e2[p2] = ((long long)__float_as_int(c2) << 32) | (unsigned)src;
        }
    }
}

// V not zeroed: first LIF writes without reading; pos-LIF overwrites all of V.
__global__ void k_cleanup() {
    int stride = gridDim.x * blockDim.x;
    for (int i = blockIdx.x * blockDim.x + threadIdx.x; i < NN; i += stride) {
        g_cnt1[i] = 0; g_cnt2[i] = 0;
        if (i < 18*2*HH) ((double*)g_stats)[i] = 0.0;
        if (i < SBLK) g_flag[i] = 0;
    }
}

// ---------------- aggregations (8-deep software pipeline) ----------------
__global__ void __launch_bounds__(256, 4) k_agg_dual(const float* __restrict__ x) {
    int lane = threadIdx.x & 31;
    int w0id = (blockIdx.x * blockDim.x + threadIdx.x) >> 5;
    int nw = (gridDim.x * blockDim.x) >> 5;
    int fc = 2 * lane;
    for (int n = w0id; n < NN; n += nw) {
        float d1 = g_dis1[n], d2 = g_dis2[n];
        float2 xx = *(const float2*)&x[n*HH + fc];
        float a10 = d1*d1*xx.x, a11 = d1*d1*xx.y;
        float a20 = d2*d2*xx.x, a21 = d2*d2*xx.y;
        int s = g_rowptr1[n], e = g_rowptr1[n+1];
        int i = s;
        if (e - s >= 8) {
            long long r0 = g_e1[i],   r1 = g_e1[i+1], r2 = g_e1[i+2], r3 = g_e1[i+3];
            long long r4 = g_e1[i+4], r5 = g_e1[i+5], r6 = g_e1[i+6], r7 = g_e1[i+7];
            for (; i + 16 <= e; i += 8) {
                float2 y0 = *(const float2*)&x[(int)r0*HH + fc];
                float2 y1 = *(const float2*)&x[(int)r1*HH + fc];
                float2 y2 = *(const float2*)&x[(int)r2*HH + fc];
                float2 y3 = *(const float2*)&x[(int)r3*HH + fc];
                float2 y4 = *(const float2*)&x[(int)r4*HH + fc];
                float2 y5 = *(const float2*)&x[(int)r5*HH + fc];
                float2 y6 = *(const float2*)&x[(int)r6*HH + fc];
                float2 y7 = *(const float2*)&x[(int)r7*HH + fc];
                long long n0 = g_e1[i+8],  n1 = g_e1[i+9],  n2 = g_e1[i+10], n3 = g_e1[i+11];
                long long n4 = g_e1[i+12], n5 = g_e1[i+13], n6 = g_e1[i+14], n7 = g_e1[i+15];
                float c0 = __int_as_float((int)(r0 >> 32));
                float c1 = __int_as_float((int)(r1 >> 32));
                float c2 = __int_as_float((int)(r2 >> 32));
                float c3 = __int_as_float((int)(r3 >> 32));
                float c4 = __int_as_float((int)(r4 >> 32));
                float c5 = __int_as_float((int)(r5 >> 32));
                float c6 = __int_as_float((int)(r6 >> 32));
                float c7 = __int_as_float((int)(r7 >> 32));
                a10 = fmaf(c0, y0.x, a10); a11 = fmaf(c0, y0.y, a11);
                a10 = fmaf(c1, y1.x, a10); a11 = fmaf(c1, y1.y, a11);
                a10 = fmaf(c2, y2.x, a10); a11 = fmaf(c2, y2.y, a11);
                a10 = fmaf(c3, y3.x, a10); a11 = fmaf(c3, y3.y, a11);
                a10 = fmaf(c4, y4.x, a10); a11 = fmaf(c4, y4.y, a11);
                a10 = fmaf(c5, y5.x, a10); a11 = fmaf(c5, y5.y, a11);
                a10 = fmaf(c6, y6.x, a10); a11 = fmaf(c6, y6.y, a11);
                a10 = fmaf(c7, y7.x, a10); a11 = fmaf(c7, y7.y, a11);
                r0 = n0; r1 = n1; r2 = n2; r3 = n3;
                r4 = n4; r5 = n5; r6 = n6; r7 = n7;
            }
            {
                float2 y0 = *(const float2*)&x[(int)r0*HH + fc];
                float2 y1 = *(const float2*)&x[(int)r1*HH + fc];
                float2 y2 = *(const float2*)&x[(int)r2*HH + fc];
                float2 y3 = *(const float2*)&x[(int)r3*HH + fc];
                float2 y4 = *(const float2*)&x[(int)r4*HH + fc];
                float2 y5 = *(const float2*)&x[(int)r5*HH + fc];
                float2 y6 = *(const float2*)&x[(int)r6*HH + fc];
                float2 y7 = *(const float2*)&x[(int)r7*HH + fc];
                float c0 = __int_as_float((int)(r0 >> 32));
                float c1 = __int_as_float((int)(r1 >> 32));
                float c2 = __int_as_float((int)(r2 >> 32));
                float c3 = __int_as_float((int)(r3 >> 32));
                float c4 = __int_as_float((int)(r4 >> 32));
                float c5 = __int_as_float((int)(r5 >> 32));
                float c6 = __int_as_float((int)(r6 >> 32));
                float c7 = __int_as_float((int)(r7 >> 32));
                a10 = fmaf(c0, y0.x, a10); a11 = fmaf(c0, y0.y, a11);
                a10 = fmaf(c1, y1.x, a10); a11 = fmaf(c1, y1.y, a11);
                a10 = fmaf(c2, y2.x, a10); a11 = fmaf(c2, y2.y, a11);
                a10 = fmaf(c3, y3.x, a10); a11 = fmaf(c3, y3.y, a11);
                a10 = fmaf(c4, y4.x, a10); a11 = fmaf(c4, y4.y, a11);
                a10 = fmaf(c5, y5.x, a10); a11 = fmaf(c5, y5.y, a11);
                a10 = fmaf(c6, y6.x, a10); a11 = fmaf(c6, y6.y, a11);
                a10 = fmaf(c7, y7.x, a10); a11 = fmaf(c7, y7.y, a11);
                i += 8;
            }
        }
        for (; i + 2 <= e; i += 2) {
            long long q0 = g_e1[i], q1 = g_e1[i+1];
            float2 y0 = *(const float2*)&x[(int)q0*HH + fc];
            float2 y1 = *(const float2*)&x[(int)q1*HH + fc];
            float c0 = __int_as_float((int)(q0 >> 32));
            float c1 = __int_as_float((int)(q1 >> 32));
            a10 = fmaf(c0, y0.x, a10); a11 = fmaf(c0, y0.y, a11);
            a10 = fmaf(c1, y1.x, a10); a11 = fmaf(c1, y1.y, a11);
        }
        for (; i < e; i++) {
            long long q = g_e1[i];
            float2 y = *(const float2*)&x[(int)q*HH + fc];
            float c = __int_as_float((int)(q >> 32));
            a10 = fmaf(c, y.x, a10); a11 = fmaf(c, y.y, a11);
        }
        s = g_rowptr2[n]; e = g_rowptr2[n+1];
        for (i = s; i + 4 <= e; i += 4) {
            long long q0 = g_e2[i],   q1 = g_e2[i+1];
            long long q2 = g_e2[i+2], q3 = g_e2[i+3];
            float2 y0 = *(const float2*)&x[(int)q0*HH + fc];
            float2 y1 = *(const float2*)&x[(int)q1*HH + fc];
            float2 y2 = *(const float2*)&x[(int)q2*HH + fc];
            float2 y3 = *(const float2*)&x[(int)q3*HH + fc];
            float c0 = __int_as_float((int)(q0 >> 32));
            float c1 = __int_as_float((int)(q1 >> 32));
            float c2 = __int_as_float((int)(q2 >> 32));
            float c3 = __int_as_float((int)(q3 >> 32));
            a20 = fmaf(c0, y0.x, a20); a21 = fmaf(c0, y0.y, a21);
            a20 = fmaf(c1, y1.x, a20); a21 = fmaf(c1, y1.y, a21);
            a20 = fmaf(c2, y2.x, a20); a21 = fmaf(c2, y2.y, a21);
            a20 = fmaf(c3, y3.x, a20); a21 = fmaf(c3, y3.y, a21);
        }
        for (; i < e; i++) {
            long long q = g_e2[i];
            float2 y = *(const float2*)&x[(int)q*HH + fc];
            float c = __int_as_float((int)(q >> 32));
            a20 = fmaf(c, y.x, a20); a21 = fmaf(c, y.y, a21);
        }
        *(float2*)&g_buf[0][n*HH+fc] = make_float2(a10, a11);
        *(float2*)&g_buf[1][n*HH+fc] = make_float2(a20, a21);
    }
}

// bf16x2 spike aggregation, 8-deep pipelined record loads
__global__ void __launch_bounds__(256, 4) k_aggbits(int pass, int outIdx) {
    int lane = threadIdx.x & 31;
    int w0id = (blockIdx.x * blockDim.x + threadIdx.x) >> 5;
    int nw = (gridDim.x * blockDim.x) >> 5;
    const int* rp = pass ? g_rowptr2 : g_rowptr1;
    const long long* ep = pass ? g_e2 : g_e1;
    for (int n = w0id; n < NN; n += nw) {
        float d = pass ? g_dis2[n] : g_dis1[n];
        float self = d*d;
        unsigned u = g_sp[n*32 + lane];
        float a0 = self * __int_as_float(u << 16);
        float a1 = self * __int_as_float(u & 0xffff0000u);
        int s = rp[n], e = rp[n+1];
        int i = s;
        if (e - s >= 8) {
            long long r0 = ep[i],   r1 = ep[i+1], r2 = ep[i+2], r3 = ep[i+3];
            long long r4 = ep[i+4], r5 = ep[i+5], r6 = ep[i+6], r7 = ep[i+7];
            for (; i + 16 <= e; i += 8) {
                unsigned u0 = g_sp[((int)r0 << 5) + lane];
                unsigned u1 = g_sp[((int)r1 << 5) + lane];
                unsigned u2 = g_sp[((int)r2 << 5) + lane];
                unsigned u3 = g_sp[((int)r3 << 5) + lane];
                unsigned u4 = g_sp[((int)r4 << 5) + lane];
                unsigned u5 = g_sp[((int)r5 << 5) + lane];
                unsigned u6 = g_sp[((int)r6 << 5) + lane];
                unsigned u7 = g_sp[((int)r7 << 5) + lane];
                long long n0 = ep[i+8],  n1 = ep[i+9],  n2 = ep[i+10], n3 = ep[i+11];
                long long n4 = ep[i+12], n5 = ep[i+13], n6 = ep[i+14], n7 = ep[i+15];
                float c0 = __int_as_float((int)(r0 >> 32));
                float c1 = __int_as_float((int)(r1 >> 32));
                float c2 = __int_as_float((int)(r2 >> 32));
                float c3 = __int_as_float((int)(r3 >> 32));
                float c4 = __int_as_float((int)(r4 >> 32));
                float c5 = __int_as_float((int)(r5 >> 32));
                float c6 = __int_as_float((int)(r6 >> 32));
                float c7 = __int_as_float((int)(r7 >> 32));
                a0 = fmaf(c0, __int_as_float(u0 << 16), a0);
                a1 = fmaf(c0, __int_as_float(u0 & 0xffff0000u), a1);
                a0 = fmaf(c1, __int_as_float(u1 << 16), a0);
                a1 = fmaf(c1, __int_as_float(u1 & 0xffff0000u), a1);
                a0 = fmaf(c2, __int_as_float(u2 << 16), a0);
                a1 = fmaf(c2, __int_as_float(u2 & 0xffff0000u), a1);
                a0 = fmaf(c3, __int_as_float(u3 << 16), a0);
                a1 = fmaf(c3, __int_as_float(u3 & 0xffff0000u), a1);
                a0 = fmaf(c4, __int_as_float(u4 << 16), a0);
                a1 = fmaf(c4, __int_as_float(u4 & 0xffff0000u), a1);
                a0 = fmaf(c5, __int_as_float(u5 << 16), a0);
                a1 = fmaf(c5, __int_as_float(u5 & 0xffff0000u), a1);
                a0 = fmaf(c6, __int_as_float(u6 << 16), a0);
                a1 = fmaf(c6, __int_as_float(u6 & 0xffff0000u), a1);
                a0 = fmaf(c7, __int_as_float(u7 << 16), a0);
                a1 = fmaf(c7, __int_as_float(u7 & 0xffff0000u), a1);
                r0 = n0; r1 = n1; r2 = n2; r3 = n3;
                r4 = n4; r5 = n5; r6 = n6; r7 = n7;
            }
            {
                unsigned u0 = g_sp[((int)r0 << 5) + lane];
                unsigned u1 = g_sp[((int)r1 << 5) + lane];
                unsigned u2 = g_sp[((int)r2 << 5) + lane];
                unsigned u3 = g_sp[((int)r3 << 5) + lane];
                unsigned u4 = g_sp[((int)r4 << 5) + lane];
                unsigned u5 = g_sp[((int)r5 << 5) + lane];
                unsigned u6 = g_sp[((int)r6 << 5) + lane];
                unsigned u7 = g_sp[((int)r7 << 5) + lane];
                float c0 = __int_as_float((int)(r0 >> 32));
                float c1 = __int_as_float((int)(r1 >> 32));
                float c2 = __int_as_float((int)(r2 >> 32));
                float c3 = __int_as_float((int)(r3 >> 32));
                float c4 = __int_as_float((int)(r4 >> 32));
                float c5 = __int_as_float((int)(r5 >> 32));
                float c6 = __int_as_float((int)(r6 >> 32));
                float c7 = __int_as_float((int)(r7 >> 32));
                a0 = fmaf(c0, __int_as_float(u0 << 16), a0);
                a1 = fmaf(c0, __int_as_float(u0 & 0xffff0000u), a1);
                a0 = fmaf(c1, __int_as_float(u1 << 16), a0);
                a1 = fmaf(c1, __int_as_float(u1 & 0xffff0000u), a1);
                a0 = fmaf(c2, __int_as_float(u2 << 16), a0);
                a1 = fmaf(c2, __int_as_float(u2 & 0xffff0000u), a1);
                a0 = fmaf(c3, __int_as_float(u3 << 16), a0);
                a1 = fmaf(c3, __int_as_float(u3 & 0xffff0000u), a1);
                a0 = fmaf(c4, __int_as_float(u4 << 16), a0);
                a1 = fmaf(c4, __int_as_float(u4 & 0xffff0000u), a1);
                a0 = fmaf(c5, __int_as_float(u5 << 16), a0);
                a1 = fmaf(c5, __int_as_float(u5 & 0xffff0000u), a1);
                a0 = fmaf(c6, __int_as_float(u6 << 16), a0);
                a1 = fmaf(c6, __int_as_float(u6 & 0xffff0000u), a1);
                a0 = fmaf(c7, __int_as_float(u7 << 16), a0);
                a1 = fmaf(c7, __int_as_float(u7 & 0xffff0000u), a1);
                i += 8;
            }
        }
        for (; i + 4 <= e; i += 4) {
            long long q0 = ep[i],   q1 = ep[i+1];
            long long q2 = ep[i+2], q3 = ep[i+3];
            unsigned u0 = g_sp[((int)q0 << 5) + lane];
            unsigned u1 = g_sp[((int)q1 << 5) + lane];
            unsigned u2 = g_sp[((int)q2 << 5) + lane];
            unsigned u3 = g_sp[((int)q3 << 5) + lane];
            float c0 = __int_as_float((int)(q0 >> 32));
            float c1 = __int_as_float((int)(q1 >> 32));
            float c2 = __int_as_float((int)(q2 >> 32));
            float c3 = __int_as_float((int)(q3 >> 32));
            a0 = fmaf(c0, __int_as_float(u0 << 16), a0);
            a1 = fmaf(c0, __int_as_float(u0 & 0xffff0000u), a1);
            a0 = fmaf(c1, __int_as_float(u1 << 16), a0);
            a1 = fmaf(c1, __int_as_float(u1 & 0xffff0000u), a1);
            a0 = fmaf(c2, __int_as_float(u2 << 16), a0);
            a1 = fmaf(c2, __int_as_float(u2 & 0xffff0000u), a1);
            a0 = fmaf(c3, __int_as_float(u3 << 16), a0);
            a1 = fmaf(c3, __int_as_float(u3 & 0xffff0000u), a1);
        }
        for (; i < e; i++) {
            long long q = ep[i];
            unsigned uu = g_sp[((int)q << 5) + lane];
            float c = __int_as_float((int)(q >> 32));
            a0 = fmaf(c, __int_as_float(uu << 16), a0);
            a1 = fmaf(c, __int_as_float(uu & 0xffff0000u), a1);
        }
        *(float2*)&g_buf[outIdx][n*HH + 2*lane] = make_float2(a0, a1);
    }
}

// ---------------- GEMM (R8/R12 design: static 48KB, native a-pairs) ----------------
__device__ __forceinline__ void gemm_body(const float* __restrict__ A,
                                          const float* __restrict__ W,
                                          const float* __restrict__ bias,
                                          float* __restrict__ Y, int st,
                                          int tid, float* As, float* Ws) {
    const float4* W4 = (const float4*)W;
    float4* Ws4 = (float4*)Ws;
    #pragma unroll
    for (int i = 0; i < 8; i++) Ws4[tid + 128*i] = W4[tid + 128*i];
    int cx = tid & 7, ry = tid >> 3;
    float b8[8];
    #pragma unroll
    for (int c = 0; c < 8; c++) b8[c] = bias[8*cx + c];
    float ls[8], lq[8];
    #pragma unroll
    for (int c = 0; c < 8; c++) { ls[c] = 0.f; lq[c] = 0.f; }

    #pragma unroll 1
    for (int t = 0; t < 2; t++) {
        int base = (blockIdx.x * 2 + t) * 128;
        __syncthreads();
        int row = base + tid;
        if (row < NN) {
            const float4* Ar = (const float4*)(A + row*HH);
            #pragma unroll
            for (int v = 0; v < 16; v++) {
                float4 q = Ar[v];
                As[(4*v+0)*128 + tid] = q.x; As[(4*v+1)*128 + tid] = q.y;
                As[(4*v+2)*128 + tid] = q.z; As[(4*v+3)*128 + tid] = q.w;
            }
        } else {
            #pragma unroll
            for (int v = 0; v < 64; v++) As[v*128 + tid] = 0.f;
        }
        __syncthreads();

        unsigned long long acc[4][8];
        #pragma unroll
        for (int p = 0; p < 4; p++)
            #pragma unroll
            for (int c = 0; c < 8; c++) acc[p][c] = 0ull;

        #pragma unroll 2
        for (int k = 0; k < 64; k++) {
            const float* ap = &As[k*128 + 8*ry];
            unsigned long long a0 = *(const unsigned long long*)(ap);
            unsigned long long a1 = *(const unsigned long long*)(ap + 2);
            unsigned long long a2 = *(const unsigned long long*)(ap + 4);
            unsigned long long a3 = *(const unsigned long long*)(ap + 6);
            float4 w0 = *(const float4*)&Ws[k*64 + 8*cx];
            float4 w1 = *(const float4*)&Ws[k*64 + 8*cx + 4];
            unsigned long long wd[8];
            wd[0] = pk2(w0.x, w0.x); wd[1] = pk2(w0.y, w0.y);
            wd[2] = pk2(w0.z, w0.z); wd[3] = pk2(w0.w, w0.w);
            wd[4] = pk2(w1.x, w1.x); wd[5] = pk2(w1.y, w1.y);
            wd[6] = pk2(w1.z, w1.z); wd[7] = pk2(w1.w, w1.w);
            #pragma unroll
            for (int c = 0; c < 8; c++) {
                fma2(acc[0][c], a0, wd[c]);
                fma2(acc[1][c], a1, wd[c]);
                fma2(acc[2][c], a2, wd[c]);
                fma2(acc[3][c], a3, wd[c]);
            }
        }
        #pragma unroll
        for (int p = 0; p < 4; p++) {
            float vlo[8], vhi[8];
            #pragma unroll
            for (int c = 0; c < 8; c++) {
                float2 tt = up2(acc[p][c]);
                vlo[c] = tt.x + b8[c];
                vhi[c] = tt.y + b8[c];
            }
            int r0 = base + 8*ry + 2*p, r1 = r0 + 1;
            if (r0 < NN) {
                #pragma unroll
                for (int c = 0; c < 8; c++) { ls[c] += vlo[c]; lq[c] = fmaf(vlo[c], vlo[c], lq[c]); }
                *(float4*)&Y[r0*HH + 8*cx]     = make_float4(vlo[0],vlo[1],vlo[2],vlo[3]);
                *(float4*)&Y[r0*HH + 8*cx + 4] = make_float4(vlo[4],vlo[5],vlo[6],vlo[7]);
            }
            if (r1 < NN) {
                #pragma unroll
                for (int c = 0; c < 8; c++) { ls[c] += vhi[c]; lq[c] = fmaf(vhi[c], vhi[c], lq[c]); }
                *(float4*)&Y[r1*HH + 8*cx]     = make_float4(vhi[0],vhi[1],vhi[2],vhi[3]);
                *(float4*)&Y[r1*HH + 8*cx + 4] = make_float4(vhi[4],vhi[5],vhi[6],vhi[7]);
            }
        }
    }
    __syncthreads();
    float* ssum = As;
    float* ssq  = As + 64;
    if (tid < 64) { ssum[tid] = 0.f; ssq[tid] = 0.f; }
    __syncthreads();
    #pragma unroll
    for (int c = 0; c < 8; c++) {
        atomicAdd(&ssum[8*cx + c], ls[c]);
        atomicAdd(&ssq[8*cx + c],  lq[c]);
    }
    __syncthreads();
    if (tid < 64) {
        atomicAdd(&g_stats[st][0][tid], (double)ssum[tid]);
        atomicAdd(&g_stats[st][1][tid], (double)ssq[tid]);
    }
}

__global__ void __launch_bounds__(128) k_gemm(int aIdx, const float* __restrict__ W,
                                              const float* __restrict__ bias,
                                              int yIdx, int st) {
    __shared__ float As[64*128];
    __shared__ float Ws[64*64];
    gemm_body(g_buf[aIdx], W, bias, g_buf[yIdx], st, threadIdx.x, As, Ws);
}

__global__ void __launch_bounds__(128) k_gemmQKV(const float* __restrict__ Wg,
                                                 const float* __restrict__ bg, int stBase) {
    __shared__ float As[64*128];
    __shared__ float Ws[64*64];
    int y = blockIdx.y;
    int outIdx = (y == 0) ? 2 : (y == 1) ? 3 : 0;
    gemm_body(g_buf[5], Wg + (3+y)*HH*HH, bg + (3+y)*HH, g_buf[outIdx],
              stBase + y, threadIdx.x, As, Ws);
}

// ---------------- BN helper ----------------
__device__ __forceinline__ float2 bn_coef(int st, int f, const float* __restrict__ g,
                                          const float* __restrict__ b) {
    double s = g_stats[st][0][f], q = g_stats[st][1][f];
    double mean = s * (1.0 / NN);
    float var = (float)(q * (1.0 / NN) - mean * mean);
    float rstd = rsqrtf(var + EPSV);
    float sc = g[f] * rstd;
    float sh = b[f] - (float)mean * sc;
    return make_float2(sc, sh);
}

__device__ __forceinline__ unsigned pack_sp(bool s0, bool s1) {
    return (s0 ? 0x00003f80u : 0u) | (s1 ? 0x3f800000u : 0u);
}

__global__ void k_lif(int yIdx, int st, const float* __restrict__ g,
                      const float* __restrict__ b, int storeIdx, int vzero) {
    int lane = threadIdx.x & 31;
    int wid = (blockIdx.x * blockDim.x + threadIdx.x) >> 5;
    int nw = (gridDim.x * blockDim.x) >> 5;
    int fc = 2 * lane;
    float2 c0 = bn_coef(st, fc, g, b);
    float2 c1 = bn_coef(st, fc + 1, g, b);
    const float* Y = g_buf[yIdx];
    for (int n = wid; n < NN; n += nw) {
        float2 y = *(const float2*)&Y[n*HH + fc];
        float x0 = fmaf(y.x, c0.x, c0.y);
        float x1 = fmaf(y.y, c1.x, c1.y);
        if (storeIdx >= 0) *(float2*)&g_buf[storeIdx][n*HH + fc] = make_float2(x0, x1);
        float v0 = x0, v1 = x1;
        if (!vzero) {
            float2 vv = *(const float2*)&g_V[n*HH + fc];
            v0 += vv.x; v1 += vv.y;
        }
        bool s0 = v0 >= THV, s1 = v1 >= THV;
        *(float2*)&g_V[n*HH + fc] = make_float2(s0 ? 0.f : v0, s1 ? 0.f : v1);
        g_sp[n*32 + lane] = pack_sp(s0, s1);
    }
}

__global__ void k_bnspike(int yIdx, int st, const float* __restrict__ g,
                          const float* __restrict__ b, int storeIdx) {
    int lane = threadIdx.x & 31;
    int wid = (blockIdx.x * blockDim.x + threadIdx.x) >> 5;
    int nw = (gridDim.x * blockDim.x) >> 5;
    int fc = 2 * lane;
    float2 c0 = bn_coef(st, fc, g, b);
    float2 c1 = bn_coef(st, fc + 1, g, b);
    const float* Y = g_buf[yIdx];
    for (int n = wid; n < NN; n += nw) {
        float2 y = *(const float2*)&Y[n*HH + fc];
        float x0 = fmaf(y.x, c0.x, c0.y);
        float x1 = fmaf(y.y, c1.x, c1.y);
        *(float2*)&g_buf[storeIdx][n*HH + fc] = make_float2(x0, x1);
        g_sp[n*32 + lane] = pack_sp(x0 >= THV, x1 >= THV);
    }
}

__global__ void k_addstats(int yIdx, int st, const float* __restrict__ g,
                           const float* __restrict__ b, int addIdx, float scale,
                           int outIdx, int stOut) {
    int lane = threadIdx.x & 31;
    int wid = (blockIdx.x * blockDim.x + threadIdx.x) >> 5;
    int nw = (gridDim.x * blockDim.x) >> 5;
    int f0 = lane, f1 = lane + 32;
    float2 c0 = bn_coef(st, f0, g, b);
    float2 c1 = bn_coef(st, f1, g, b);
    const float* Y = g_buf[yIdx];
    const float* Ad = g_buf[addIdx];
    float* O = g_buf[outIdx];
    float ls0 = 0.f, lq0 = 0.f, ls1 = 0.f, lq1 = 0.f;
    for (int n = wid; n < NN; n += nw) {
        float t0 = fmaf(scale, fmaf(Y[n*HH+f0], c0.x, c0.y), Ad[n*HH+f0]);
        float t1 = fmaf(scale, fmaf(Y[n*HH+f1], c1.x, c1.y), Ad[n*HH+f1]);
        O[n*HH+f0] = t0; O[n*HH+f1] = t1;
        ls0 += t0; lq0 = fmaf(t0, t0, lq0);
        ls1 += t1; lq1 = fmaf(t1, t1, lq1);
    }
    __shared__ float ss[64], sq[64];
    if (threadIdx.x < 64) { ss[threadIdx.x] = 0.f; sq[threadIdx.x] = 0.f; }
    __syncthreads();
    atomicAdd(&ss[f0], ls0); atomicAdd(&sq[f0], lq0);
    atomicAdd(&ss[f1], ls1); atomicAdd(&sq[f1], lq1);
    __syncthreads();
    if (threadIdx.x < 64) {
        atomicAdd(&g_stats[stOut][0][threadIdx.x], (double)ss[threadIdx.x]);
        atomicAdd(&g_stats[stOut][1][threadIdx.x], (double)sq[threadIdx.x]);
    }
}

__global__ void k_qkv(int stq, int stk, int stv,
                      const float* __restrict__ bng, const float* __restrict__ bnb) {
    int lane = threadIdx.x & 31;
    int wid = (blockIdx.x * blockDim.x + threadIdx.x) >> 5;
    int nw = (gridDim.x * blockDim.x) >> 5;
    int fc = 2 * lane;
    float2 q0 = bn_coef(stq, fc,   bng + 4*HH, bnb + 4*HH);
    float2 q1 = bn_coef(stq, fc+1, bng + 4*HH, bnb + 4*HH);
    float2 k0 = bn_coef(stk, fc,   bng + 5*HH, bnb + 5*HH);
    float2 k1 = bn_coef(stk, fc+1, bng + 5*HH, bnb + 5*HH);
    float2 v0 = bn_coef(stv, fc,   bng + 6*HH, bnb + 6*HH);
    float2 v1 = bn_coef(stv, fc+1, bng + 6*HH, bnb + 6*HH);
    const float* Yq = g_buf[2];
    const float* Yk = g_buf[3];
    const float* Yv = g_buf[0];
    for (int n = wid; n < NN; n += nw) {
        float2 yq = *(const float2*)&Yq[n*HH + fc];
        float2 yk = *(const float2*)&Yk[n*HH + fc];
        float2 yv = *(const float2*)&Yv[n*HH + fc];
        bool qa = fmaf(yq.x, q0.x, q0.y) >= THV, qb = fmaf(yq.y, q1.x, q1.y) >= THV;
        bool ka = fmaf(yk.x, k0.x, k0.y) >= THV, kb = fmaf(yk.y, k1.x, k1.y) >= THV;
        bool va = fmaf(yv.x, v0.x, v0.y) >= THV, vb = fmaf(yv.y, v1.x, v1.y) >= THV;
        unsigned b0 = __ballot_sync(0xffffffffu, qa && ka);
        unsigned b1 = __ballot_sync(0xffffffffu, qb && kb);
        int pc = __popc(b0) + __popc(b1);
        bool att = ((float)pc * (1.0f / 64.0f)) >= ATTV;
        g_sp[n*32 + lane] = att ? pack_sp(va, vb) : 0u;
    }
}

__global__ void k_dec(int tIdx, int st, const float* __restrict__ g,
                      const float* __restrict__ b, float* __restrict__ out) {
    int lane = threadIdx.x & 31;
    int wid = (blockIdx.x * blockDim.x + threadIdx.x) >> 5;
    int nw = (gridDim.x * blockDim.x) >> 5;
    int f0 = lane, f1 = lane + 32;
    float2 c0 = bn_coef(st, f0, g, b);
    float2 c1 = bn_coef(st, f1, g, b);
    const float* T = g_buf[tIdx];
    float w0 = g_wsum[f0], w1 = g_wsum[f1];
    for (int n = wid; n < NN; n += nw) {
        float s = (fmaf(T[n*HH+f0], c0.x, c0.y)) * w0 + (fmaf(T[n*HH+f1], c1.x, c1.y)) * w1;
        #pragma unroll
        for (int o = 16; o > 0; o >>= 1) s += __shfl_down_sync(0xffffffffu, s, o);
        if (lane == 0) out[n] = s;
    }
}

// ---------------- host orchestration ----------------
static void run_enc(int p, const float* Wg, const float* bg,
                    const float* bng, const float* bnb, float* out) {
    int base = 9 * p;
    const int T = 256;
    k_gemm<<<391, 128>>>(p, Wg + 0*HH*HH, bg + 0*HH, 2, base + 0);
    k_lif<<<EB, T>>>(2, base + 0, bng + 0*HH, bnb + 0*HH, -1, p == 0 ? 1 : 0);
    k_aggbits<<<AGB, T>>>(p, 5);
    k_gemm<<<391, 128>>>(5, Wg + 1*HH*HH, bg + 1*HH, 2, base + 1);
    k_bnspike<<<EB, T>>>(2, base + 1, bng + 1*HH, bnb + 1*HH, 3);
    k_aggbits<<<AGB, T>>>(p, 5);
    k_gemm<<<391, 128>>>(5, Wg + 2*HH*HH, bg + 2*HH, 2, base + 2);
    k_addstats<<<EB, T>>>(2, base + 2, bng + 2*HH, bnb + 2*HH, 3, 1.0f, 4, base + 3);
    k_lif<<<EB, T>>>(4, base + 3, bng + 3*HH, bnb + 3*HH, 4, 0);
    k_aggbits<<<AGB, T>>>(p, 5);
    k_gemmQKV<<<dim3(391, 3), 128>>>(Wg, bg, base + 4);
    k_qkv<<<EB, T>>>(base + 4, base + 5, base + 6, bng, bnb);
    k_aggbits<<<AGB, T>>>(p, 5);
    k_gemm<<<391, 128>>>(5, Wg + 6*HH*HH, bg + 6*HH, 2, base + 7);
    k_addstats<<<EB, T>>>(2, base + 7, bng + 7*HH, bnb + 7*HH, 4, 0.125f, 3, base + 8);
    k_dec<<<EB, T>>>(3, base + 8, bng + 8*HH, bnb + 8*HH, out);
}

extern "C" void kernel_launch(void* const* d_in, const int* in_sizes, int n_in,
                              void* d_out, int out_size) {
    const float* x   = (const float*)d_in[0];
    const int*   ei  = (const int*)d_in[1];
    const int*   mk  = (const int*)d_in[2];
    const float* Wg  = (const float*)d_in[3];
    const float* bg  = (const float*)d_in[4];
    const float* bng = (const float*)d_in[5];
    const float* bnb = (const float*)d_in[6];
    const float* Wl  = (const float*)d_in[7];
    float* out = (float*)d_out;

    k_count<<<EB, 256>>>(ei, mk, Wl);   // 0
    k_scan<<<SBLK, 1024>>>();           // 1
    k_scatter<<<EB, 256>>>(ei, mk);     // 2
    k_agg_dual<<<EB, 256>>>(x);         // 3  <- profiled
    run_enc(0, Wg, bg, bng, bnb, out);
    run_enc(1, Wg, bg, bng, bnb, out + NN);
    k_cleanup<<<EB, 256>>>();
}

// round 16
// speedup vs baseline: 1.0525x; 1.0525x over previous
#include <cuda_runtime.h>

#define NN 100000
#define EE 1600000
#define HH 64
#define THV 0.7f
#define ATTV 0.2f
#define EPSV 1e-5f
#define SBLK 98
#define EB 1184
#define AGB 888

__device__ float g_buf[6][NN*HH];
__device__ float g_V[NN*HH];
__device__ unsigned g_sp[NN*32];          // bf16x2 spikes: lane l -> cols (2l, 2l+1)
__device__ int g_cnt1[NN], g_cnt2[NN];
__device__ int g_rowptr1[NN+1], g_cursor1[NN];
__device__ int g_rowptr2[NN+1], g_cursor2[NN];
__device__ long long g_e1[EE];            // {coef_bits:hi, src:lo}
__device__ long long g_e2[EE];            // masked edges only
__device__ float g_dis1[NN], g_dis2[NN];
__device__ double g_stats[18][2][HH];
__device__ float g_wsum[HH];
__device__ int g_agg1[SBLK], g_agg2[SBLK], g_flag[SBLK];

// ---------------- f32x2 helpers ----------------
__device__ __forceinline__ unsigned long long pk2(float x, float y) {
    unsigned long long r; asm("mov.b64 %0,{%1,%2};" : "=l"(r) : "f"(x), "f"(y)); return r;
}
__device__ __forceinline__ float2 up2(unsigned long long v) {
    float2 r; asm("mov.b64 {%0,%1},%2;" : "=f"(r.x), "=f"(r.y) : "l"(v)); return r;
}
__device__ __forceinline__ void fma2(unsigned long long& d, unsigned long long a, unsigned long long b) {
    asm("fma.rn.f32x2 %0,%1,%2,%0;" : "+l"(d) : "l"(a), "l"(b));
}

// ---------------- setup ----------------
__global__ void k_count(const int* __restrict__ ei, const int* __restrict__ mk,
                        const float* __restrict__ Wl) {
    int stride = gridDim.x * blockDim.x;
    for (int e = blockIdx.x * blockDim.x + threadIdx.x; e < EE; e += stride) {
        int dst = ei[EE + e];
        atomicAdd(&g_cnt1[dst], 1);
        if (mk[e]) atomicAdd(&g_cnt2[dst], 1);
    }
    if (blockIdx.x == 0 && threadIdx.x < HH) {
        float s = 0.f;
        for (int j = 0; j < HH; j++) s += Wl[threadIdx.x*HH + j];
        g_wsum[threadIdx.x] = s;
    }
}

__device__ __forceinline__ int blk_scan(int v, int t, int* sw) {
    int x = v;
    #pragma unroll
    for (int o = 1; o < 32; o <<= 1) {
        int y = __shfl_up_sync(0xffffffffu, x, o);
        if ((t & 31) >= o) x += y;
    }
    if ((t & 31) == 31) sw[t >> 5] = x;
    __syncthreads();
    if (t < 32) {
        int y = sw[t], z = y;
        #pragma unroll
        for (int o = 1; o < 32; o <<= 1) {
            int w = __shfl_up_sync(0xffffffffu, z, o);
            if (t >= o) z += w;
        }
        sw[t] = z - y;
    }
    __syncthreads();
    return x + sw[t >> 5];
}

__global__ void k_scan() {
    __shared__ int sw1[32], sw2[32];
    __shared__ int soff1, soff2;
    int t = threadIdx.x, b = blockIdx.x;
    int i = b * 1024 + t;
    int c1 = (i < NN) ? g_cnt1[i] : 0;
    int c2 = (i < NN) ? g_cnt2[i] : 0;
    int incl1 = blk_scan(c1, t, sw1);
    __syncthreads();
    int incl2 = blk_scan(c2, t, sw2);
    if (t == 1023) {
        atomicExch(&g_agg1[b], incl1);
        atomicExch(&g_agg2[b], incl2);
        __threadfence();
        atomicExch(&g_flag[b], 1);
    }
    if (t < 32) {
        int o1 = 0, o2 = 0;
        for (int j = t; j < b; j += 32) {
            while (atomicAdd(&g_flag[j], 0) == 0) { }
            o1 += atomicAdd(&g_agg1[j], 0);
            o2 += atomicAdd(&g_agg2[j], 0);
        }
        #pragma unroll
        for (int o = 16; o > 0; o >>= 1) {
            o1 += __shfl_down_sync(0xffffffffu, o1, o);
            o2 += __shfl_down_sync(0xffffffffu, o2, o);
        }
        if (t == 0) { soff1 = o1; soff2 = o2; }
    }
    __syncthreads();
    if (i < NN) {
        int r1 = soff1 + incl1 - c1;
        int r2 = soff2 + incl2 - c2;
        g_rowptr1[i] = r1; g_cursor1[i] = r1;
        g_rowptr2[i] = r2; g_cursor2[i] = r2;
        g_dis1[i] = rsqrtf(1.0f + (float)c1);
        g_dis2[i] = rsqrtf(1.0f + (float)c2);
    }
    if (b == SBLK - 1 && t == 1023) {
        g_rowptr1[NN] = soff1 + incl1;
        g_rowptr2[NN] = soff2 + incl2;
    }
}

__global__ void k_scatter(const int* __restrict__ ei, const int* __restrict__ mk) {
    int stride = gridDim.x * blockDim.x;
    for (int e = blockIdx.x * blockDim.x + threadIdx.x; e < EE; e += stride) {
        int src = ei[e], dst = ei[EE + e];
        float c1 = g_dis1[src] * g_dis1[dst];
        int p1 = atomicAdd(&g_cursor1[dst], 1);
        g_e1[p1] = ((long long)__float_as_int(c1) << 32) | (unsigned)src;
        if (mk[e]) {
            float c2 = g_dis2[src] * g_dis2[dst];
            int p2 = atomicAdd(&g_cursor2[dst], 1);
            g_e2[p2] = ((long long)__float_as_int(c2) << 32) | (unsigned)src;
        }
    }
}

// V not zeroed: first LIF writes without reading; pos-LIF overwrites all of V.
__global__ void k_cleanup() {
    int stride = gridDim.x * blockDim.x;
    for (int i = blockIdx.x * blockDim.x + threadIdx.x; i < NN; i += stride) {
        g_cnt1[i] = 0; g_cnt2[i] = 0;
        if (i < 18*2*HH) ((double*)g_stats)[i] = 0.0;
        if (i < SBLK) g_flag[i] = 0;
    }
}

// ---------------- aggregations (R12 configuration) ----------------
__global__ void k_agg_dual(const float* __restrict__ x) {
    int lane = threadIdx.x & 31;
    int w0id = (blockIdx.x * blockDim.x + threadIdx.x) >> 5;
    int nw = (gridDim.x * blockDim.x) >> 5;
    int fc = 2 * lane;
    for (int n = w0id; n < NN; n += nw) {
        float d1 = g_dis1[n], d2 = g_dis2[n];
        float2 xx = *(const float2*)&x[n*HH + fc];
        float a10 = d1*d1*xx.x, a11 = d1*d1*xx.y;
        float a20 = d2*d2*xx.x, a21 = d2*d2*xx.y;
        int s = g_rowptr1[n], e = g_rowptr1[n+1];
        int i = s;
        for (; i + 4 <= e; i += 4) {
            long long q0 = g_e1[i],   q1 = g_e1[i+1];
            long long q2 = g_e1[i+2], q3 = g_e1[i+3];
            float2 y0 = *(const float2*)&x[(int)q0*HH + fc];
            float2 y1 = *(const float2*)&x[(int)q1*HH + fc];
            float2 y2 = *(const float2*)&x[(int)q2*HH + fc];
            float2 y3 = *(const float2*)&x[(int)q3*HH + fc];
            float c0 = __int_as_float((int)(q0 >> 32));
            float c1 = __int_as_float((int)(q1 >> 32));
            float c2 = __int_as_float((int)(q2 >> 32));
            float c3 = __int_as_float((int)(q3 >> 32));
            a10 = fmaf(c0, y0.x, a10); a11 = fmaf(c0, y0.y, a11);
            a10 = fmaf(c1, y1.x, a10); a11 = fmaf(c1, y1.y, a11);
            a10 = fmaf(c2, y2.x, a10); a11 = fmaf(c2, y2.y, a11);
            a10 = fmaf(c3, y3.x, a10); a11 = fmaf(c3, y3.y, a11);
        }
        for (; i < e; i++) {
            long long q = g_e1[i];
            float2 y = *(const float2*)&x[(int)q*HH + fc];
            float c = __int_as_float((int)(q >> 32));
            a10 = fmaf(c, y.x, a10); a11 = fmaf(c, y.y, a11);
        }
        s = g_rowptr2[n]; e = g_rowptr2[n+1];
        for (i = s; i + 2 <= e; i += 2) {
            long long q0 = g_e2[i], q1 = g_e2[i+1];
            float2 y0 = *(const float2*)&x[(int)q0*HH + fc];
            float2 y1 = *(const float2*)&x[(int)q1*HH + fc];
            float c0 = __int_as_float((int)(q0 >> 32));
            float c1 = __int_as_float((int)(q1 >> 32));
            a20 = fmaf(c0, y0.x, a20); a21 = fmaf(c0, y0.y, a21);
            a20 = fmaf(c1, y1.x, a20); a21 = fmaf(c1, y1.y, a21);
        }
        for (; i < e; i++) {
            long long q = g_e2[i];
            float2 y = *(const float2*)&x[(int)q*HH + fc];
            float c = __int_as_float((int)(q >> 32));
            a20 = fmaf(c, y.x, a20); a21 = fmaf(c, y.y, a21);
        }
        *(float2*)&g_buf[0][n*HH+fc] = make_float2(a10, a11);
        *(float2*)&g_buf[1][n*HH+fc] = make_float2(a20, a21);
    }
}

// bf16x2 spike aggregation, depth-2 pipelined record loads (R12 config)
__global__ void __launch_bounds__(256, 6) k_aggbits(int pass, int outIdx) {
    int lane = threadIdx.x & 31;
    int w0id = (blockIdx.x * blockDim.x + threadIdx.x) >> 5;
    int nw = (gridDim.x * blockDim.x) >> 5;
    const int* rp = pass ? g_rowptr2 : g_rowptr1;
    const long long* ep = pass ? g_e2 : g_e1;
    for (int n = w0id; n < NN; n += nw) {
        float d = pass ? g_dis2[n] : g_dis1[n];
        float self = d*d;
        unsigned u = g_sp[n*32 + lane];
        float a0 = self * __int_as_float(u << 16);
        float a1 = self * __int_as_float(u & 0xffff0000u);
        int s = rp[n], e = rp[n+1];
        int i = s;
        if (i + 4 <= e) {
            long long r0 = ep[i], r1 = ep[i+1], r2 = ep[i+2], r3 = ep[i+3];
            for (; i + 8 <= e; i += 4) {
                unsigned u0 = g_sp[((int)r0 << 5) + lane];
                unsigned u1 = g_sp[((int)r1 << 5) + lane];
                unsigned u2 = g_sp[((int)r2 << 5) + lane];
                unsigned u3 = g_sp[((int)r3 << 5) + lane];
                long long n0 = ep[i+4], n1 = ep[i+5], n2 = ep[i+6], n3 = ep[i+7];
                float c0 = __int_as_float((int)(r0 >> 32));
                float c1 = __int_as_float((int)(r1 >> 32));
                float c2 = __int_as_float((int)(r2 >> 32));
                float c3 = __int_as_float((int)(r3 >> 32));
                a0 = fmaf(c0, __int_as_float(u0 << 16), a0);
                a1 = fmaf(c0, __int_as_float(u0 & 0xffff0000u), a1);
                a0 = fmaf(c1, __int_as_float(u1 << 16), a0);
                a1 = fmaf(c1, __int_as_float(u1 & 0xffff0000u), a1);
                a0 = fmaf(c2, __int_as_float(u2 << 16), a0);
                a1 = fmaf(c2, __int_as_float(u2 & 0xffff0000u), a1);
                a0 = fmaf(c3, __int_as_float(u3 << 16), a0);
                a1 = fmaf(c3, __int_as_float(u3 & 0xffff0000u), a1);
                r0 = n0; r1 = n1; r2 = n2; r3 = n3;
            }
            {
                unsigned u0 = g_sp[((int)r0 << 5) + lane];
                unsigned u1 = g_sp[((int)r1 << 5) + lane];
                unsigned u2 = g_sp[((int)r2 << 5) + lane];
                unsigned u3 = g_sp[((int)r3 << 5) + lane];
                float c0 = __int_as_float((int)(r0 >> 32));
                float c1 = __int_as_float((int)(r1 >> 32));
                float c2 = __int_as_float((int)(r2 >> 32));
                float c3 = __int_as_float((int)(r3 >> 32));
                a0 = fmaf(c0, __int_as_float(u0 << 16), a0);
                a1 = fmaf(c0, __int_as_float(u0 & 0xffff0000u), a1);
                a0 = fmaf(c1, __int_as_float(u1 << 16), a0);
                a1 = fmaf(c1, __int_as_float(u1 & 0xffff0000u), a1);
                a0 = fmaf(c2, __int_as_float(u2 << 16), a0);
                a1 = fmaf(c2, __int_as_float(u2 & 0xffff0000u), a1);
                a0 = fmaf(c3, __int_as_float(u3 << 16), a0);
                a1 = fmaf(c3, __int_as_float(u3 & 0xffff0000u), a1);
                i += 4;
            }
        }
        for (; i < e; i++) {
            long long q = ep[i];
            unsigned uu = g_sp[((int)q << 5) + lane];
            float c = __int_as_float((int)(q >> 32));
            a0 = fmaf(c, __int_as_float(uu << 16), a0);
            a1 = fmaf(c, __int_as_float(uu & 0xffff0000u), a1);
        }
        *(float2*)&g_buf[outIdx][n*HH + 2*lane] = make_float2(a0, a1);
    }
}

// ---------------- GEMM (R8/R12 design: static 48KB, native a-pairs) ----------------
__device__ __forceinline__ void gemm_body(const float* __restrict__ A,
                                          const float* __restrict__ W,
                                          const float* __restrict__ bias,
                                          float* __restrict__ Y, int st,
                                          int tid, float* As, float* Ws) {
    const float4* W4 = (const float4*)W;
    float4* Ws4 = (float4*)Ws;
    #pragma unroll
    for (int i = 0; i < 8; i++) Ws4[tid + 128*i] = W4[tid + 128*i];
    int cx = tid & 7, ry = tid >> 3;
    float b8[8];
    #pragma unroll
    for (int c = 0; c < 8; c++) b8[c] = bias[8*cx + c];
    float ls[8], lq[8];
    #pragma unroll
    for (int c = 0; c < 8; c++) { ls[c] = 0.f; lq[c] = 0.f; }

    #pragma unroll 1
    for (int t = 0; t < 2; t++) {
        int base = (blockIdx.x * 2 + t) * 128;
        __syncthreads();
        int row = base + tid;
        if (row < NN) {
            const float4* Ar = (const float4*)(A + row*HH);
            #pragma unroll
            for (int v = 0; v < 16; v++) {
                float4 q = Ar[v];
                As[(4*v+0)*128 + tid] = q.x; As[(4*v+1)*128 + tid] = q.y;
                As[(4*v+2)*128 + tid] = q.z; As[(4*v+3)*128 + tid] = q.w;
            }
        } else {
            #pragma unroll
            for (int v = 0; v < 64; v++) As[v*128 + tid] = 0.f;
        }
        __syncthreads();

        unsigned long long acc[4][8];
        #pragma unroll
        for (int p = 0; p < 4; p++)
            #pragma unroll
            for (int c = 0; c < 8; c++) acc[p][c] = 0ull;

        #pragma unroll 2
        for (int k = 0; k < 64; k++) {
            const float* ap = &As[k*128 + 8*ry];
            unsigned long long a0 = *(const unsigned long long*)(ap);
            unsigned long long a1 = *(const unsigned long long*)(ap + 2);
            unsigned long long a2 = *(const unsigned long long*)(ap + 4);
            unsigned long long a3 = *(const unsigned long long*)(ap + 6);
            float4 w0 = *(const float4*)&Ws[k*64 + 8*cx];
            float4 w1 = *(const float4*)&Ws[k*64 + 8*cx + 4];
            unsigned long long wd[8];
            wd[0] = pk2(w0.x, w0.x); wd[1] = pk2(w0.y, w0.y);
            wd[2] = pk2(w0.z, w0.z); wd[3] = pk2(w0.w, w0.w);
            wd[4] = pk2(w1.x, w1.x); wd[5] = pk2(w1.y, w1.y);
            wd[6] = pk2(w1.z, w1.z); wd[7] = pk2(w1.w, w1.w);
            #pragma unroll
            for (int c = 0; c < 8; c++) {
                fma2(acc[0][c], a0, wd[c]);
                fma2(acc[1][c], a1, wd[c]);
                fma2(acc[2][c], a2, wd[c]);
                fma2(acc[3][c], a3, wd[c]);
            }
        }
        #pragma unroll
        for (int p = 0; p < 4; p++) {
            float vlo[8], vhi[8];
            #pragma unroll
            for (int c = 0; c < 8; c++) {
                float2 tt = up2(acc[p][c]);
                vlo[c] = tt.x + b8[c];
                vhi[c] = tt.y + b8[c];
            }
            int r0 = base + 8*ry + 2*p, r1 = r0 + 1;
            if (r0 < NN) {
                #pragma unroll
                for (int c = 0; c < 8; c++) { ls[c] += vlo[c]; lq[c] = fmaf(vlo[c], vlo[c], lq[c]); }
                *(float4*)&Y[r0*HH + 8*cx]     = make_float4(vlo[0],vlo[1],vlo[2],vlo[3]);
                *(float4*)&Y[r0*HH + 8*cx + 4] = make_float4(vlo[4],vlo[5],vlo[6],vlo[7]);
            }
            if (r1 < NN) {
                #pragma unroll
                for (int c = 0; c < 8; c++) { ls[c] += vhi[c]; lq[c] = fmaf(vhi[c], vhi[c], lq[c]); }
                *(float4*)&Y[r1*HH + 8*cx]     = make_float4(vhi[0],vhi[1],vhi[2],vhi[3]);
                *(float4*)&Y[r1*HH + 8*cx + 4] = make_float4(vhi[4],vhi[5],vhi[6],vhi[7]);
            }
        }
    }
    __syncthreads();
    float* ssum = As;
    float* ssq  = As + 64;
    if (tid < 64) { ssum[tid] = 0.f; ssq[tid] = 0.f; }
    __syncthreads();
    #pragma unroll
    for (int c = 0; c < 8; c++) {
        atomicAdd(&ssum[8*cx + c], ls[c]);
        atomicAdd(&ssq[8*cx + c],  lq[c]);
    }
    __syncthreads();
    if (tid < 64) {
        atomicAdd(&g_stats[st][0][tid], (double)ssum[tid]);
        atomicAdd(&g_stats[st][1][tid], (double)ssq[tid]);
    }
}

__global__ void __launch_bounds__(128) k_gemm(int aIdx, const float* __restrict__ W,
                                              const float* __restrict__ bias,
                                              int yIdx, int st) {
    __shared__ float As[64*128];
    __shared__ float Ws[64*64];
    gemm_body(g_buf[aIdx], W, bias, g_buf[yIdx], st, threadIdx.x, As, Ws);
}

__global__ void __launch_bounds__(128) k_gemmQKV(const float* __restrict__ Wg,
                                                 const float* __restrict__ bg, int stBase) {
    __shared__ float As[64*128];
    __shared__ float Ws[64*64];
    int y = blockIdx.y;
    int outIdx = (y == 0) ? 2 : (y == 1) ? 3 : 0;
    gemm_body(g_buf[5], Wg + (3+y)*HH*HH, bg + (3+y)*HH, g_buf[outIdx],
              stBase + y, threadIdx.x, As, Ws);
}

// ---------------- BN helper ----------------
__device__ __forceinline__ float2 bn_coef(int st, int f, const float* __restrict__ g,
                                          const float* __restrict__ b) {
    double s = g_stats[st][0][f], q = g_stats[st][1][f];
    double mean = s * (1.0 / NN);
    float var = (float)(q * (1.0 / NN) - mean * mean);
    float rstd = rsqrtf(var + EPSV);
    float sc = g[f] * rstd;
    float sh = b[f] - (float)mean * sc;
    return make_float2(sc, sh);
}

__device__ __forceinline__ unsigned pack_sp(bool s0, bool s1) {
    return (s0 ? 0x00003f80u : 0u) | (s1 ? 0x3f800000u : 0u);
}

__global__ void k_lif(int yIdx, int st, const float* __restrict__ g,
                      const float* __restrict__ b, int storeIdx, int vzero) {
    int lane = threadIdx.x & 31;
    int wid = (blockIdx.x * blockDim.x + threadIdx.x) >> 5;
    int nw = (gridDim.x * blockDim.x) >> 5;
    int fc = 2 * lane;
    float2 c0 = bn_coef(st, fc, g, b);
    float2 c1 = bn_coef(st, fc + 1, g, b);
    const float* Y = g_buf[yIdx];
    for (int n = wid; n < NN; n += nw) {
        float2 y = *(const float2*)&Y[n*HH + fc];
        float x0 = fmaf(y.x, c0.x, c0.y);
        float x1 = fmaf(y.y, c1.x, c1.y);
        if (storeIdx >= 0) *(float2*)&g_buf[storeIdx][n*HH + fc] = make_float2(x0, x1);
        float v0 = x0, v1 = x1;
        if (!vzero) {
            float2 vv = *(const float2*)&g_V[n*HH + fc];
            v0 += vv.x; v1 += vv.y;
        }
        bool s0 = v0 >= THV, s1 = v1 >= THV;
        *(float2*)&g_V[n*HH + fc] = make_float2(s0 ? 0.f : v0, s1 ? 0.f : v1);
        g_sp[n*32 + lane] = pack_sp(s0, s1);
    }
}

__global__ void k_bnspike(int yIdx, int st, const float* __restrict__ g,
                          const float* __restrict__ b, int storeIdx) {
    int lane = threadIdx.x & 31;
    int wid = (blockIdx.x * blockDim.x + threadIdx.x) >> 5;
    int nw = (gridDim.x * blockDim.x) >> 5;
    int fc = 2 * lane;
    float2 c0 = bn_coef(st, fc, g, b);
    float2 c1 = bn_coef(st, fc + 1, g, b);
    const float* Y = g_buf[yIdx];
    for (int n = wid; n < NN; n += nw) {
        float2 y = *(const float2*)&Y[n*HH + fc];
        float x0 = fmaf(y.x, c0.x, c0.y);
        float x1 = fmaf(y.y, c1.x, c1.y);
        *(float2*)&g_buf[storeIdx][n*HH + fc] = make_float2(x0, x1);
        g_sp[n*32 + lane] = pack_sp(x0 >= THV, x1 >= THV);
    }
}

__global__ void k_addstats(int yIdx, int st, const float* __restrict__ g,
                           const float* __restrict__ b, int addIdx, float scale,
                           int outIdx, int stOut) {
    int lane = threadIdx.x & 31;
    int wid = (blockIdx.x * blockDim.x + threadIdx.x) >> 5;
    int nw = (gridDim.x * blockDim.x) >> 5;
    int fc = 2 * lane;
    float2 c0 = bn_coef(st, fc, g, b);
    float2 c1 = bn_coef(st, fc + 1, g, b);
    const float* Y = g_buf[yIdx];
    const float* Ad = g_buf[addIdx];
    float* O = g_buf[outIdx];
    float ls0 = 0.f, lq0 = 0.f, ls1 = 0.f, lq1 = 0.f;
    for (int n = wid; n < NN; n += nw) {
        float2 y = *(const float2*)&Y[n*HH + fc];
        float2 ad = *(const float2*)&Ad[n*HH + fc];
        float t0 = fmaf(scale, fmaf(y.x, c0.x, c0.y), ad.x);
        float t1 = fmaf(scale, fmaf(y.y, c1.x, c1.y), ad.y);
        *(float2*)&O[n*HH + fc] = make_float2(t0, t1);
        ls0 += t0; lq0 = fmaf(t0, t0, lq0);
        ls1 += t1; lq1 = fmaf(t1, t1, lq1);
    }
    __shared__ float ss[64], sq[64];
    if (threadIdx.x < 64) { ss[threadIdx.x] = 0.f; sq[threadIdx.x] = 0.f; }
    __syncthreads();
    atomicAdd(&ss[fc], ls0); atomicAdd(&sq[fc], lq0);
    atomicAdd(&ss[fc+1], ls1); atomicAdd(&sq[fc+1], lq1);
    __syncthreads();
    if (threadIdx.x < 64) {
        atomicAdd(&g_stats[stOut][0][threadIdx.x], (double)ss[threadIdx.x]);
        atomicAdd(&g_stats[stOut][1][threadIdx.x], (double)sq[threadIdx.x]);
    }
}

__global__ void k_qkv(int stq, int stk, int stv,
                      const float* __restrict__ bng, const float* __restrict__ bnb) {
    int lane = threadIdx.x & 31;
    int wid = (blockIdx.x * blockDim.x + threadIdx.x) >> 5;
    int nw = (gridDim.x * blockDim.x) >> 5;
    int fc = 2 * lane;
    float2 q0 = bn_coef(stq, fc,   bng + 4*HH, bnb + 4*HH);
    float2 q1 = bn_coef(stq, fc+1, bng + 4*HH, bnb + 4*HH);
    float2 k0 = bn_coef(stk, fc,   bng + 5*HH, bnb + 5*HH);
    float2 k1 = bn_coef(stk, fc+1, bng + 5*HH, bnb + 5*HH);
    float2 v0 = bn_coef(stv, fc,   bng + 6*HH, bnb + 6*HH);
    float2 v1 = bn_coef(stv, fc+1, bng + 6*HH, bnb + 6*HH);
    const float* Yq = g_buf[2];
    const float* Yk = g_buf[3];
    const float* Yv = g_buf[0];
    for (int n = wid; n < NN; n += nw) {
        float2 yq = *(const float2*)&Yq[n*HH + fc];
        float2 yk = *(const float2*)&Yk[n*HH + fc];
        float2 yv = *(const float2*)&Yv[n*HH + fc];
        bool qa = fmaf(yq.x, q0.x, q0.y) >= THV, qb = fmaf(yq.y, q1.x, q1.y) >= THV;
        bool ka = fmaf(yk.x, k0.x, k0.y) >= THV, kb = fmaf(yk.y, k1.x, k1.y) >= THV;
        bool va = fmaf(yv.x, v0.x, v0.y) >= THV, vb = fmaf(yv.y, v1.x, v1.y) >= THV;
        unsigned b0 = __ballot_sync(0xffffffffu, qa && ka);
        unsigned b1 = __ballot_sync(0xffffffffu, qb && kb);
        int pc = __popc(b0) + __popc(b1);
        bool att = ((float)pc * (1.0f / 64.0f)) >= ATTV;
        g_sp[n*32 + lane] = att ? pack_sp(va, vb) : 0u;
    }
}

__global__ void k_dec(int tIdx, int st, const float* __restrict__ g,
                      const float* __restrict__ b, float* __restrict__ out) {
    int lane = threadIdx.x & 31;
    int wid = (blockIdx.x * blockDim.x + threadIdx.x) >> 5;
    int nw = (gridDim.x * blockDim.x) >> 5;
    int fc = 2 * lane;
    float2 c0 = bn_coef(st, fc, g, b);
    float2 c1 = bn_coef(st, fc + 1, g, b);
    const float* T = g_buf[tIdx];
    float w0 = g_wsum[fc], w1 = g_wsum[fc + 1];
    for (int n = wid; n < NN; n += nw) {
        float2 t = *(const float2*)&T[n*HH + fc];
        float s = fmaf(t.x, c0.x, c0.y) * w0 + fmaf(t.y, c1.x, c1.y) * w1;
        #pragma unroll
        for (int o = 16; o > 0; o >>= 1) s += __shfl_down_sync(0xffffffffu, s, o);
        if (lane == 0) out[n] = s;
    }
}

// ---------------- host orchestration ----------------
static void run_enc(int p, const float* Wg, const float* bg,
                    const float* bng, const float* bnb, float* out) {
    int base = 9 * p;
    const int T = 256;
    k_gemm<<<391, 128>>>(p, Wg + 0*HH*HH, bg + 0*HH, 2, base + 0);
    k_lif<<<EB, T>>>(2, base + 0, bng + 0*HH, bnb + 0*HH, -1, p == 0 ? 1 : 0);
    k_aggbits<<<AGB, T>>>(p, 5);
    k_gemm<<<391, 128>>>(5, Wg + 1*HH*HH, bg + 1*HH, 2, base + 1);
    k_bnspike<<<EB, T>>>(2, base + 1, bng + 1*HH, bnb + 1*HH, 3);
    k_aggbits<<<AGB, T>>>(p, 5);
    k_gemm<<<391, 128>>>(5, Wg + 2*HH*HH, bg + 2*HH, 2, base + 2);
    k_addstats<<<EB, T>>>(2, base + 2, bng + 2*HH, bnb + 2*HH, 3, 1.0f, 4, base + 3);
    k_lif<<<EB, T>>>(4, base + 3, bng + 3*HH, bnb + 3*HH, 4, 0);
    k_aggbits<<<AGB, T>>>(p, 5);
    k_gemmQKV<<<dim3(391, 3), 128>>>(Wg, bg, base + 4);
    k_qkv<<<EB, T>>>(base + 4, base + 5, base + 6, bng, bnb);
    k_aggbits<<<AGB, T>>>(p, 5);
    k_gemm<<<391, 128>>>(5, Wg + 6*HH*HH, bg + 6*HH, 2, base + 7);
    k_addstats<<<EB, T>>>(2, base + 7, bng + 7*HH, bnb + 7*HH, 4, 0.125f, 3, base + 8);
    k_dec<<<EB, T>>>(3, base + 8, bng + 8*HH, bnb + 8*HH, out);
}

extern "C" void kernel_launch(void* const* d_in, const int* in_sizes, int n_in,
                              void* d_out, int out_size) {
    const float* x   = (const float*)d_in[0];
    const int*   ei  = (const int*)d_in[1];
    const int*   mk  = (const int*)d_in[2];
    const float* Wg  = (const float*)d_in[3];
    const float* bg  = (const float*)d_in[4];
    const float* bng = (const float*)d_in[5];
    const float* bnb = (const float*)d_in[6];
    const float* Wl  = (const float*)d_in[7];
    float* out = (float*)d_out;

    k_count<<<EB, 256>>>(ei, mk, Wl);   // 0
    k_scan<<<SBLK, 1024>>>();           // 1
    k_scatter<<<EB, 256>>>(ei, mk);     // 2
    k_agg_dual<<<EB, 256>>>(x);         // 3  <- profiled
    run_enc(0, Wg, bg, bng, bnb, out);
    run_enc(1, Wg, bg, bng, bnb, out + NN);
    k_cleanup<<<EB, 256>>>();
}